// round 8
// baseline (speedup 1.0000x reference)
#include <cuda_runtime.h>
#include <cuda_fp16.h>
#include <cstdint>

// ============================================================================
// out_i = || P * U(params) * s_i ||^2, 131072 states of dim 256.
// params batch-invariant -> precompute A = P*U (128x256 complex), then a real
// fp16 mma.sync GEMM (tcgen05 unavailable on compute_103 base target):
//   S = [sr | si] (131072 x 512 fp32 -> fp16 on the fly)
//   Wh[n][k] fp16 (256 x 512), n<128: [Ar | -Ai], n>=128: [Ai | Ar]
//   C[m][n] = sum_k S[m][k] Wh[n][k];  out_m = sum_n C[m][n]^2
//
// R8: R7 design with the smem offset double-count fixed (aRow/bRow carry the
//     wg / OFF_B bases exactly once; stage offsets are relative).
//     B resident in SMEM (N-half 128 x K 512 = 128KB, loaded once; mainloop
//     has zero cp.async / CP_WAIT). CTA = two INDEPENDENT 128-thread
//     warpgroups (named barriers, no CTA-wide sync in mainloop). Warp tile
//     64x64. Outputs combined across N-halves via atomicAdd (out zeroed in
//     the setup kernel).
// ============================================================================

#define NLAYERS 3
#define NQ 8

__device__ __half Wh_global[256 * 512];

// ---------------------------------------------------------------------------
__device__ __forceinline__ uint32_t smem_u32(const void* p) {
    uint32_t a;
    asm("{ .reg .u64 t; cvta.to.shared.u64 t, %1; cvt.u32.u64 %0, t; }"
        : "=r"(a) : "l"(p));
    return a;
}

__device__ __forceinline__ void ldmatrix_x4(uint32_t r[4], uint32_t addr) {
    asm volatile("ldmatrix.sync.aligned.m8n8.x4.shared.b16 {%0,%1,%2,%3}, [%4];"
                 : "=r"(r[0]), "=r"(r[1]), "=r"(r[2]), "=r"(r[3]) : "r"(addr));
}

__device__ __forceinline__ void mma16816(float c[4], const uint32_t a[4],
                                         uint32_t b0, uint32_t b1) {
    asm volatile(
        "mma.sync.aligned.m16n8k16.row.col.f32.f16.f16.f32 "
        "{%0,%1,%2,%3}, {%4,%5,%6,%7}, {%8,%9}, {%0,%1,%2,%3};"
        : "+f"(c[0]), "+f"(c[1]), "+f"(c[2]), "+f"(c[3])
        : "r"(a[0]), "r"(a[1]), "r"(a[2]), "r"(a[3]), "r"(b0), "r"(b1));
}

__device__ __forceinline__ void cp_async16(uint32_t dst, const void* src) {
    asm volatile("cp.async.cg.shared.global [%0], [%1], 16;"
                 :: "r"(dst), "l"(src) : "memory");
}
#define CP_COMMIT() asm volatile("cp.async.commit_group;" ::: "memory")
#define CP_WAIT0()  asm volatile("cp.async.wait_group 0;" ::: "memory")
#define WG_BAR(id)  asm volatile("bar.sync %0, 128;" :: "r"(id) : "memory")

// ---------------------------------------------------------------------------
// Setup: block k simulates basis state |k> (gates from smem, trig once per
// block). Also zero-initializes d_out (poisoned by harness; qmm atomicAdds).
// ---------------------------------------------------------------------------
__global__ void build_weights_kernel(const float* __restrict__ params,
                                     float* __restrict__ out_zero) {
    __shared__ float2 st[256];
    __shared__ float g[NLAYERS * NQ][8];
    int k = blockIdx.x;
    int t = threadIdx.x;

    // zero d_out: 256 blocks x 256 thr x 2 = 131072
    int zi = blockIdx.x * 256 + t;
    out_zero[zi] = 0.0f;
    out_zero[zi + 65536] = 0.0f;

    if (t < NLAYERS * NQ) {
        const float* pr = params + t * 3;
        float hx = 0.5f * pr[0], hy = 0.5f * pr[1], hz = 0.5f * pr[2];
        float cx = cosf(hx), sx = sinf(hx);
        float cy = cosf(hy), sy = sinf(hy);
        float cz = cosf(hz), sz = sinf(hz);
        float m00r =  cy * cx, m00i =  sy * sx;
        float m01r = -sy * cx, m01i = -cy * sx;
        float m10r =  sy * cx, m10i = -cy * sx;
        float m11r =  cy * cx, m11i = -sy * sx;
        g[t][0] = cz * m00r + sz * m00i;  g[t][1] = cz * m00i - sz * m00r;
        g[t][2] = cz * m01r + sz * m01i;  g[t][3] = cz * m01i - sz * m01r;
        g[t][4] = cz * m10r - sz * m10i;  g[t][5] = cz * m10i + sz * m10r;
        g[t][6] = cz * m11r - sz * m11i;  g[t][7] = cz * m11i + sz * m11r;
    }
    st[t] = make_float2(t == k ? 1.0f : 0.0f, 0.0f);
    __syncthreads();

    for (int l = 0; l < NLAYERS; l++) {
        for (int q = 0; q < NQ; q++) {
            const float* u = g[l * NQ + q];
            float u00r = u[0], u00i = u[1], u01r = u[2], u01i = u[3];
            float u10r = u[4], u10i = u[5], u11r = u[6], u11i = u[7];
            int p = 7 - q;  // qubit 0 = MSB of flat index
            if (t < 128) {
                int lo = t & ((1 << p) - 1);
                int i0 = ((t >> p) << (p + 1)) | lo;
                int i1 = i0 | (1 << p);
                float2 a0 = st[i0], a1 = st[i1];
                float2 n0, n1;
                n0.x = u00r*a0.x - u00i*a0.y + u01r*a1.x - u01i*a1.y;
                n0.y = u00r*a0.y + u00i*a0.x + u01r*a1.y + u01i*a1.x;
                n1.x = u10r*a0.x - u10i*a0.y + u11r*a1.x - u11i*a1.y;
                n1.y = u10r*a0.y + u10i*a0.x + u11r*a1.y + u11i*a1.x;
                st[i0] = n0;
                st[i1] = n1;
            }
            __syncthreads();
        }
        for (int q = 0; q < NQ; q++) {
            int pc = 7 - q;
            int pt = 7 - ((q + 1) & 7);
            if (((t >> pc) & 1) == 1 && ((t >> pt) & 1) == 0) {
                int j = t | (1 << pt);
                float2 tmp = st[t];
                st[t] = st[j];
                st[j] = tmp;
            }
            __syncthreads();
        }
    }
    if (t < 128) {
        float re = st[t].x, im = st[t].y;
        Wh_global[t * 512 + k]               = __float2half_rn(re);
        Wh_global[t * 512 + 256 + k]         = __float2half_rn(-im);
        Wh_global[(128 + t) * 512 + k]       = __float2half_rn(im);
        Wh_global[(128 + t) * 512 + 256 + k] = __float2half_rn(re);
    }
}

// ---------------------------------------------------------------------------
// GEMM: grid = 512 m-tiles x 2 n-halves. CTA = 256 rows x 128 N-half cols,
// 256 threads = 2 warpgroups x 4 warps. Warpgroup wg owns rows wg*128..+127
// with its own A double-buffer and named barrier; warp grid inside wg is
// 2(M) x 2(N), warp tile 64x64. B (128 x 512 fp16 = 128KB, 8 chunk-blocks of
// [128 rows x 128B]) is loaded once and stays resident.
// SMEM: A = [0,64KB): wg*32KB + stage*16KB;  B = [64KB,192KB): chunk*16KB.
// ---------------------------------------------------------------------------
static constexpr uint32_t OFF_B    = 64 * 1024;
static constexpr uint32_t DYN_SMEM = 192 * 1024 + 1024;

__global__ void __launch_bounds__(256, 1)
qmm_kernel(const float* __restrict__ sre, const float* __restrict__ sim,
           float* __restrict__ out) {
    extern __shared__ char smem_raw[];
    uint32_t base  = smem_u32(smem_raw);
    uint32_t abase = (base + 1023u) & ~1023u;
    char* a = smem_raw + (abase - base);

    const int tid   = threadIdx.x;
    const int wid   = tid >> 5;
    const int lane  = tid & 31;
    const int wg    = wid >> 2;      // warpgroup 0/1
    const int wgtid = tid & 127;
    const int wm    = (wid >> 1) & 1;  // m-half within wg
    const int wn    = wid & 1;         // n-half within wg

    const int  mtile = blockIdx.x >> 1;
    const int  nh    = blockIdx.x & 1;
    const long wgBase = (long)mtile * 256 + wg * 128;  // global row base of wg

    // ldmatrix per-lane geometry
    const int r  = lane & 7;
    const int q  = lane >> 3;
    const uint32_t xorv = (uint32_t)r << 4;
    const uint32_t ch16 = (uint32_t)(q >> 1) << 4;
    const int rl = ((q & 1) << 3) + r;

    // Bases carry wg / OFF_B exactly once; stage offsets are RELATIVE.
    const uint32_t aWg = abase + (uint32_t)wg * 32768u;
    uint32_t aRow[4], bRow[4];
    #pragma unroll
    for (int mf = 0; mf < 4; mf++)
        aRow[mf] = aWg + (uint32_t)(wm * 64 + mf * 16 + rl) * 128;
    #pragma unroll
    for (int nb = 0; nb < 4; nb++)
        bRow[nb] = abase + OFF_B + (uint32_t)(wn * 64 + nb * 16 + rl) * 128;

    // ---- B resident load (CTA-wide): 8192 x 16B, 256 thr -> 32 each ----
    #pragma unroll
    for (int it = 0; it < 32; it++) {
        int i = tid + it * 256;
        int c = i >> 10;            // chunk block
        int j = i & 1023;
        int n = j >> 3, seg = j & 7;
        uint32_t dst = abase + OFF_B + (uint32_t)c * 16384u +
                       (uint32_t)n * 128 +
                       (((uint32_t)seg * 16) ^ (((uint32_t)n & 7) << 4));
        cp_async16(dst, Wh_global + (nh * 128 + n) * 512 + c * 64 + seg * 8);
    }
    CP_COMMIT();

    float acc[4][8][4];
    #pragma unroll
    for (int mf = 0; mf < 4; mf++)
        #pragma unroll
        for (int nf = 0; nf < 8; nf++)
            #pragma unroll
            for (int i = 0; i < 4; i++) acc[mf][nf][i] = 0.0f;

    float4 av[8];

    // A load/store helpers (wg-local; 128 rows x 16 float4 = 2048 per chunk,
    // 128 threads -> 2 batches of 8)
    auto ldg_batch = [&](int cn, int b) {
        const float* src = (cn < 4) ? sre : sim;
        int cb = (cn & 3) * 64;
        #pragma unroll
        for (int it = 0; it < 8; it++) {
            int i = wgtid + it * 128 + b * 1024;
            int row = i >> 4, f4 = i & 15;
            av[it] = *(const float4*)(src + (wgBase + row) * 256 + cb + f4 * 4);
        }
    };
    auto sts_batch = [&](int cn, int b) {
        uint32_t saoff = (uint32_t)wg * 32768u + (uint32_t)(cn & 1) * 16384u;
        #pragma unroll
        for (int it = 0; it < 8; it++) {
            int i = wgtid + it * 128 + b * 1024;
            int row = i >> 4, f4 = i & 15;
            __half2 p0 = __floats2half2_rn(av[it].x, av[it].y);
            __half2 p1 = __floats2half2_rn(av[it].z, av[it].w);
            uint2 u;
            u.x = *(const uint32_t*)&p0;
            u.y = *(const uint32_t*)&p1;
            uint32_t byte = (uint32_t)row * 128 +
                            (((uint32_t)f4 * 8) ^ (((uint32_t)row & 7) << 4));
            *(uint2*)(a + saoff + byte) = u;
        }
    };
    // saoff_rel: (c&1)*16KB ;  sboff_rel: c*16KB  (bases already in aRow/bRow)
    auto compute_ks = [&](uint32_t saoff_rel, uint32_t sboff_rel, int ks) {
        uint32_t cx = (((uint32_t)ks * 32) | ch16) ^ xorv;
        uint32_t af[4][4];
        #pragma unroll
        for (int mf = 0; mf < 4; mf++)
            ldmatrix_x4(af[mf], aRow[mf] + saoff_rel + cx);
        uint32_t bf[4][4];
        #pragma unroll
        for (int nb = 0; nb < 4; nb++)
            ldmatrix_x4(bf[nb], bRow[nb] + sboff_rel + cx);
        #pragma unroll
        for (int mf = 0; mf < 4; mf++)
            #pragma unroll
            for (int nf = 0; nf < 8; nf++) {
                int nb = nf >> 1, sub = nf & 1;
                mma16816(acc[mf][nf], af[mf], bf[nb][sub], bf[nb][sub + 2]);
            }
    };

    // ---- A prologue: chunk 0 into stage 0 (wg-local, serial) ----
    ldg_batch(0, 0);
    sts_batch(0, 0);
    ldg_batch(0, 1);
    sts_batch(0, 1);

    CP_WAIT0();          // B resident
    __syncthreads();     // B visible + own A stage-0 visible to the wg

    const int bar_id = wg + 1;

    // ---- mainloop: 8 chunks of K=64, no CTA-wide syncs ----
    for (int c = 0; c < 8; c++) {
        uint32_t saoff = (uint32_t)(c & 1) * 16384u;   // relative A stage
        uint32_t sboff = (uint32_t)c * 16384u;         // relative B chunk

        if (c < 7) ldg_batch(c + 1, 0);
        compute_ks(saoff, sboff, 0);
        compute_ks(saoff, sboff, 1);
        if (c < 7) { sts_batch(c + 1, 0); ldg_batch(c + 1, 1); }
        compute_ks(saoff, sboff, 2);
        compute_ks(saoff, sboff, 3);
        if (c < 7) sts_batch(c + 1, 1);
        WG_BAR(bar_id);
    }

    // ---- epilogue: out[m] += sum_n C[m][n]^2 (this N-half's partial) ----
    #pragma unroll
    for (int mf = 0; mf < 4; mf++) {
        float s_lo = 0.0f, s_hi = 0.0f;
        #pragma unroll
        for (int nf = 0; nf < 8; nf++) {
            s_lo = fmaf(acc[mf][nf][0], acc[mf][nf][0], s_lo);
            s_lo = fmaf(acc[mf][nf][1], acc[mf][nf][1], s_lo);
            s_hi = fmaf(acc[mf][nf][2], acc[mf][nf][2], s_hi);
            s_hi = fmaf(acc[mf][nf][3], acc[mf][nf][3], s_hi);
        }
        s_lo += __shfl_xor_sync(0xFFFFFFFF, s_lo, 1);
        s_lo += __shfl_xor_sync(0xFFFFFFFF, s_lo, 2);
        s_hi += __shfl_xor_sync(0xFFFFFFFF, s_hi, 1);
        s_hi += __shfl_xor_sync(0xFFFFFFFF, s_hi, 2);
        if ((lane & 3) == 0) {
            long row = wgBase + wm * 64 + mf * 16 + (lane >> 2);
            atomicAdd(out + row, s_lo);
            atomicAdd(out + row + 8, s_hi);
        }
    }
}

// ---------------------------------------------------------------------------
extern "C" void kernel_launch(void* const* d_in, const int* in_sizes, int n_in,
                              void* d_out, int out_size) {
    const float* params = (const float*)d_in[0];
    const float* sre    = (const float*)d_in[1];
    const float* sim    = (const float*)d_in[2];
    float* out = (float*)d_out;

    cudaFuncSetAttribute(qmm_kernel, cudaFuncAttributeMaxDynamicSharedMemorySize,
                         DYN_SMEM);

    build_weights_kernel<<<256, 256>>>(params, out);
    qmm_kernel<<<1024, 256, DYN_SMEM>>>(sre, sim, out);
}